// round 8
// baseline (speedup 1.0000x reference)
#include <cuda_runtime.h>
#include <cuda_fp16.h>
#include <cstdint>
#include <cstddef>

// out = relu(x[131072,256] @ W[256,256]^T + b[256]), fp32 in/out.
// fp16 mma.m16n8k16. Full-residency CTA: 128(M)x256(N), K=256 entirely in smem
// (217KB), 512 threads, 1 CTA/SM. All B cp.async groups issued up front; A
// staged via pipelined LDG+cvt+STS in the prologue. Mainloop: pure ldm+MMA
// with register fragment double-buffer; 4 cheap rendezvous barriers.

#define DEVI __device__ __forceinline__

static constexpr int M_TOTAL = 131072;
static constexpr int N = 256;
static constexpr int K = 256;
static constexpr int BM = 128;
static constexpr int KC = 64;
static constexpr int KTILES = K / KC;            // 4
static constexpr int STRB = 144;                 // smem row stride bytes
static constexpr int A_STAGE = BM * STRB;        // 18432
static constexpr int B_STAGE = N * STRB;         // 36864
static constexpr int SM_TILES = 1024;
static constexpr int A_BASE = SM_TILES;
static constexpr int B_BASE = SM_TILES + KTILES * A_STAGE;        // 74752
static constexpr int SMEM_TOTAL = B_BASE + KTILES * B_STAGE;      // 222208

__device__ __half g_wh[N * K];

DEVI uint32_t smem_u32(const void* p) {
    uint32_t a;
    asm("{ .reg .u64 t; cvta.to.shared.u64 t, %1; cvt.u32.u64 %0, t; }"
        : "=r"(a) : "l"(p));
    return a;
}

DEVI void cp16(uint32_t dst, const void* src) {
    asm volatile("cp.async.cg.shared.global [%0], [%1], 16;"
                 :: "r"(dst), "l"(__cvta_generic_to_global(src)) : "memory");
}

template <int Npend> DEVI void cp_wait() {
    asm volatile("cp.async.wait_group %0;" :: "n"(Npend) : "memory");
}

DEVI uint32_t pack_h2(float lo, float hi) {
    uint32_t r;
    asm("cvt.rn.f16x2.f32 %0, %1, %2;" : "=r"(r) : "f"(hi), "f"(lo));
    return r;
}

DEVI void ldm_x4(uint32_t* r, uint32_t addr) {
    asm volatile("ldmatrix.sync.aligned.m8n8.x4.shared.b16 {%0,%1,%2,%3}, [%4];"
                 : "=r"(r[0]), "=r"(r[1]), "=r"(r[2]), "=r"(r[3]) : "r"(addr));
}

DEVI void mma_f16(float* c, const uint32_t* a, const uint32_t* b) {
    asm volatile(
        "mma.sync.aligned.m16n8k16.row.col.f32.f16.f16.f32 "
        "{%0,%1,%2,%3}, {%4,%5,%6,%7}, {%8,%9}, {%0,%1,%2,%3};"
        : "+f"(c[0]), "+f"(c[1]), "+f"(c[2]), "+f"(c[3])
        : "r"(a[0]), "r"(a[1]), "r"(a[2]), "r"(a[3]), "r"(b[0]), "r"(b[1]));
}

__global__ void convert_w_kernel(const float* __restrict__ W) {
    int idx4 = (blockIdx.x * 256 + threadIdx.x) * 4;
    float4 v = *reinterpret_cast<const float4*>(W + idx4);
    uint2 h;
    h.x = pack_h2(v.x, v.y);
    h.y = pack_h2(v.z, v.w);
    *reinterpret_cast<uint2*>(g_wh + idx4) = h;
}

__global__ void __launch_bounds__(512, 1)
gemm_f16_kernel(const float* __restrict__ x,
                const float* __restrict__ bias,
                float* __restrict__ out) {
    extern __shared__ char smem[];
    float* sbias = reinterpret_cast<float*>(smem);
    const uint32_t sbase = smem_u32(smem);
    const int tid  = threadIdx.x;
    const int lane = tid & 31;
    const int wid  = tid >> 5;
    const int warp_m = wid >> 2;       // 0..3 (32 M rows each)
    const int warp_n = wid & 3;        // 0..3 (64 N cols each)
    const int gid = lane >> 2;
    const int tg  = lane & 3;

    const int m_base = blockIdx.x * BM;

    if (tid < N) sbias[tid] = bias[tid];

    const uint32_t aOff = (uint32_t)((warp_m * 32 + (lane & 15)) * STRB
                                     + ((lane >> 4) * 8) * 2);
    const uint32_t bOff = (uint32_t)((warp_n * 64 + (lane & 7) + ((lane >> 4) << 3)) * STRB
                                     + (((lane >> 3) & 1) * 8) * 2);

    float acc[2][8][4];
    #pragma unroll
    for (int mt = 0; mt < 2; ++mt)
        #pragma unroll
        for (int nt = 0; nt < 8; ++nt)
            #pragma unroll
            for (int j = 0; j < 4; ++j)
                acc[mt][nt][j] = 0.0f;

    // loader indices (512 threads)
    const int ar = tid >> 4;           // A row 0..31 (+32 per i)
    const int ac = tid & 15;           // 16B src / 8B dst granule
    const int br = tid >> 3;           // B row 0..63 (+64 per i)
    const int bc = tid & 7;

    auto load_B = [&](int kt) {        // one commit group per kt
        const __half* srcB = g_wh + kt * KC;
        uint32_t dB = sbase + B_BASE + kt * B_STAGE;
        #pragma unroll
        for (int i = 0; i < 4; ++i) {
            int r = br + i * 64;
            cp16(dB + r * STRB + bc * 16, srcB + (size_t)r * K + bc * 8);
        }
        asm volatile("cp.async.commit_group;" ::: "memory");
    };

    auto ldg_A = [&](int kt, float4* pf) {
        const float* srcA = x + (size_t)m_base * K + kt * KC;
        #pragma unroll
        for (int i = 0; i < 4; ++i)
            pf[i] = *reinterpret_cast<const float4*>(srcA + (size_t)(ar + i * 32) * K + ac * 4);
    };

    auto sts_A = [&](int kt, const float4* pf) {
        char* dA = smem + A_BASE + kt * A_STAGE;
        #pragma unroll
        for (int i = 0; i < 4; ++i) {
            uint2 h;
            h.x = pack_h2(pf[i].x, pf[i].y);
            h.y = pack_h2(pf[i].z, pf[i].w);
            *reinterpret_cast<uint2*>(dA + (ar + i * 32) * STRB + ac * 8) = h;
        }
    };

    // ---- Prologue: deep-prefetch everything ----
    load_B(0); load_B(1); load_B(2); load_B(3);
    {
        float4 p0[4], p1[4];
        ldg_A(0, p0); ldg_A(1, p1);
        sts_A(0, p0); ldg_A(2, p0);
        sts_A(1, p1); ldg_A(3, p1);
        sts_A(2, p0);
        sts_A(3, p1);
    }

    // ---- Mainloop: 4 K-chunks, no smem writes, rendezvous barriers ----
    #pragma unroll
    for (int kt = 0; kt < KTILES; ++kt) {
        if (kt == 0)      cp_wait<3>();
        else if (kt == 1) cp_wait<2>();
        else if (kt == 2) cp_wait<1>();
        else              cp_wait<0>();
        __syncthreads();

        const uint32_t aBase = sbase + A_BASE + kt * A_STAGE + aOff;
        const uint32_t bBase = sbase + B_BASE + kt * B_STAGE + bOff;

        uint32_t a[2][2][4], b[2][4][4];
        ldm_x4(a[0][0], aBase);
        ldm_x4(a[0][1], aBase + 16 * STRB);
        #pragma unroll
        for (int j = 0; j < 4; ++j)
            ldm_x4(b[0][j], bBase + (16 * j) * STRB);

        #pragma unroll
        for (int ks = 0; ks < 4; ++ks) {
            const int cur = ks & 1, nxt = cur ^ 1;
            if (ks < 3) {
                ldm_x4(a[nxt][0], aBase + (ks + 1) * 32);
                ldm_x4(a[nxt][1], aBase + 16 * STRB + (ks + 1) * 32);
                #pragma unroll
                for (int j = 0; j < 4; ++j)
                    ldm_x4(b[nxt][j], bBase + (16 * j) * STRB + (ks + 1) * 32);
            }
            #pragma unroll
            for (int mt = 0; mt < 2; ++mt)
                #pragma unroll
                for (int nt = 0; nt < 8; ++nt)
                    mma_f16(acc[mt][nt], a[cur][mt], &b[cur][nt >> 1][(nt & 1) * 2]);
        }
    }

    // ---- Epilogue: bias + relu; float2 stores ----
    #pragma unroll
    for (int mt = 0; mt < 2; ++mt) {
        int r0 = m_base + warp_m * 32 + mt * 16 + gid;
        float* o0 = out + (size_t)r0 * N;
        float* o1 = out + (size_t)(r0 + 8) * N;
        #pragma unroll
        for (int nt = 0; nt < 8; ++nt) {
            int c = warp_n * 64 + nt * 8 + 2 * tg;
            float b0 = sbias[c], b1 = sbias[c + 1];
            float2 v0, v1;
            v0.x = fmaxf(acc[mt][nt][0] + b0, 0.0f);
            v0.y = fmaxf(acc[mt][nt][1] + b1, 0.0f);
            v1.x = fmaxf(acc[mt][nt][2] + b0, 0.0f);
            v1.y = fmaxf(acc[mt][nt][3] + b1, 0.0f);
            *reinterpret_cast<float2*>(o0 + c) = v0;
            *reinterpret_cast<float2*>(o1 + c) = v1;
        }
    }
}

extern "C" void kernel_launch(void* const* d_in, const int* in_sizes, int n_in,
                              void* d_out, int out_size) {
    const float* x = (const float*)d_in[0];
    const float* W = (const float*)d_in[1];
    const float* b = (const float*)d_in[2];
    float* out = (float*)d_out;

    convert_w_kernel<<<64, 256>>>(W);

    cudaFuncSetAttribute(gemm_f16_kernel,
                         cudaFuncAttributeMaxDynamicSharedMemorySize, SMEM_TOTAL);
    gemm_f16_kernel<<<M_TOTAL / BM, 512, SMEM_TOTAL>>>(x, b, out);
}